// round 9
// baseline (speedup 1.0000x reference)
#include <cuda_runtime.h>
#include <cstdint>

// REWAEncoder: out = (FWHT_128(x @ W^T)/sqrt(128) > 0)
// R9: one-level Strassen fp32 GEMM (7/8 of the MACs) + FWHT + sign.
//   A = x: M split 16384|16384, K split 512|512. B = W^T: K split, N split 64|64.
//   Each CTA: 64 virtual rows -> 128 real output rows (top+bottom), computes
//   P1..P7 sequentially, accumulates +-P into a C smem buffer, FWHT, sign.
//   V-combos (B side) precomputed by prep kernel; U-combos (A side) formed in
//   staging (2 LDG + FADD). Rows with min|h| < TAU recomputed bit-exactly with
//   the reference sequential fp32 fma chain (machinery: rel_err 0.0 in R7/R8).
//
// x [32768,1024] f32, W [128,1024] f32, out [32768,128] f32.

#define K_DIM 1024
#define MOUT  128
#define NROWS 32768
#define MHALF 16384
#define KHALF 512
#define NHALF 64
#define TAU   3e-4f

__device__ __align__(16) float g_V[7 * KHALF * NHALF];   // [j][k][n], k-major
__device__ int g_flags[NROWS];

// smem: hb[128][132] C-buffer (67584 B), then As[16][64], Vs[16][64]
#define HB_PITCH 132
#define SM_HB    0
#define SM_AS    (128 * HB_PITCH * 4)            // 67584
#define SM_VS    (SM_AS + 16 * 64 * 4)           // +4096
#define SM_TOTAL (SM_VS + 16 * 64 * 4)           // 75776 B

// ---------------- prep: Strassen B-combos from W ----------------
// V1=B11+B22  V2=B11  V3=B12-B22  V4=B21-B11  V5=B22  V6=B11+B12  V7=B21+B22
// with B[k][n] = W[n][k]:  B11=W[n][k] B12=W[64+n][k] B21=W[n][512+k] B22=W[64+n][512+k]
__global__ void prep_v_kernel(const float* __restrict__ W) {
    const int idx = blockIdx.x * blockDim.x + threadIdx.x;  // 0..229375
    const int j = idx / (KHALF * NHALF);
    const int r = idx % (KHALF * NHALF);
    const int k = r / NHALF;
    const int n = r % NHALF;
    const float b11 = W[(size_t)n * K_DIM + k];
    const float b12 = W[(size_t)(n + NHALF) * K_DIM + k];
    const float b21 = W[(size_t)n * K_DIM + k + KHALF];
    const float b22 = W[(size_t)(n + NHALF) * K_DIM + k + KHALF];
    float v;
    switch (j) {
        case 0: v = b11 + b22; break;
        case 1: v = b11;       break;
        case 2: v = b12 - b22; break;
        case 3: v = b21 - b11; break;
        case 4: v = b22;       break;
        case 5: v = b11 + b12; break;
        default: v = b21 + b22; break;
    }
    g_V[idx] = v;
}

// ---------------- main: Strassen GEMM + FWHT + sign + flag ----------------
__global__ void __launch_bounds__(256, 2)
strassen_kernel(const float* __restrict__ x, float* __restrict__ out) {
    extern __shared__ __align__(16) char smem[];
    float (*hb)[HB_PITCH] = reinterpret_cast<float(*)[HB_PITCH]>(smem + SM_HB);
    float (*As)[64] = reinterpret_cast<float(*)[64]>(smem + SM_AS);  // [k][vr]
    float (*Vs)[64] = reinterpret_cast<float(*)[64]>(smem + SM_VS);  // [k][n]

    const int tid = threadIdx.x;
    const int tr  = tid >> 4;         // 0..15 -> vrows tr*4..+3
    const int tc  = tid & 15;         // 0..15 -> cols  tc*4..+3
    const int br  = blockIdx.x * 64;  // virtual-row base

    // staging ids
    const int sv = tid >> 2;          // vr 0..63
    const int sq = tid & 3;           // k-float4 index
    const int kk = tid >> 4;          // V: k 0..15
    const int nn = (tid & 15) * 4;    // V: n

    // U-combo LUTs (P1..P7): U = x[t1-half][c1+k] + s2 * x[t2-half][c2+k]
    const int U_t1[7] = {0, 1, 0, 1, 0, 1, 0};
    const int U_c1[7] = {0, 0, 0, KHALF, 0, 0, KHALF};
    const int U_s2[7] = {1, 1, 0, 0, 1, -1, -1};
    const int U_t2[7] = {1, 1, 0, 0, 0, 0, 1};
    const int U_c2[7] = {KHALF, KHALF, 0, 0, KHALF, 0, KHALF};
    // C placements: (row-off, col-off, sign), 2 slots (sign 0 = unused)
    // C11=P1+P4-P5+P7  C12=P3+P5  C21=P2+P4  C22=P1-P2+P3+P6
    const int P_r0[7] = {0, 64, 0, 0, 0, 64, 0};
    const int P_c0[7] = {0, 0, 64, 0, 0, 64, 0};
    const int P_s0[7] = {1, 1, 1, 1, -1, 1, 1};
    const int P_r1[7] = {64, 64, 64, 64, 0, 0, 0};
    const int P_c1[7] = {64, 64, 64, 0, 64, 0, 0};
    const int P_s1[7] = {1, -1, 1, 1, 1, 0, 0};

    // zero the C buffer
    for (int i = tid; i < 128 * HB_PITCH; i += 256)
        ((float*)hb)[i] = 0.0f;

    float pacc[4][4];

    // load U/V float4s for (j, chunk c)
    auto load_uv = [&](int j, int c, float4& u, float4& vv) {
        const int kb = c * 16;
        const size_t r1 = (size_t)(U_t1[j] ? MHALF : 0) + br + sv;
        const float4 a1 = *(const float4*)(x + r1 * K_DIM + U_c1[j] + kb + sq * 4);
        const int s2 = U_s2[j];
        if (s2 != 0) {
            const size_t r2 = (size_t)(U_t2[j] ? MHALF : 0) + br + sv;
            const float4 a2 = *(const float4*)(x + r2 * K_DIM + U_c2[j] + kb + sq * 4);
            const float fs = (float)s2;
            u.x = fmaf(fs, a2.x, a1.x); u.y = fmaf(fs, a2.y, a1.y);
            u.z = fmaf(fs, a2.z, a1.z); u.w = fmaf(fs, a2.w, a1.w);
        } else {
            u = a1;
        }
        vv = *(const float4*)(g_V + ((size_t)j * KHALF + kb + kk) * NHALF + nn);
    };

    float4 u, vv;
    load_uv(0, 0, u, vv);

    for (int idx = 0; idx < 7 * 32; ++idx) {
        const int j = idx >> 5;
        const int c = idx & 31;
        if (c == 0) {
#pragma unroll
            for (int i = 0; i < 4; ++i)
#pragma unroll
                for (int q = 0; q < 4; ++q) pacc[i][q] = 0.0f;
        }
        __syncthreads();             // prior chunk's tile reads done
        // stage current chunk
        As[sq * 4 + 0][sv] = u.x; As[sq * 4 + 1][sv] = u.y;
        As[sq * 4 + 2][sv] = u.z; As[sq * 4 + 3][sv] = u.w;
        *(float4*)&Vs[kk][nn] = vv;
        __syncthreads();
        // prefetch next (j', c') while computing
        if (idx + 1 < 7 * 32)
            load_uv((idx + 1) >> 5, (idx + 1) & 31, u, vv);

#pragma unroll
        for (int k = 0; k < 16; ++k) {
            const float4 a = *(const float4*)&As[k][tr * 4];
            const float4 b = *(const float4*)&Vs[k][tc * 4];
            const float av[4] = {a.x, a.y, a.z, a.w};
            const float bv[4] = {b.x, b.y, b.z, b.w};
#pragma unroll
            for (int i = 0; i < 4; ++i)
#pragma unroll
                for (int q = 0; q < 4; ++q)
                    pacc[i][q] = fmaf(av[i], bv[q], pacc[i][q]);
        }

        if (c == 31) {
            // place +-P_j into C buffer; each thread owns its cells -> race-free
            {
                const float fs = (float)P_s0[j];
                const int ro = P_r0[j] + tr * 4, co = P_c0[j] + tc * 4;
#pragma unroll
                for (int i = 0; i < 4; ++i)
#pragma unroll
                    for (int q = 0; q < 4; ++q)
                        hb[ro + i][co + q] += fs * pacc[i][q];
            }
            if (P_s1[j] != 0) {
                const float fs = (float)P_s1[j];
                const int ro = P_r1[j] + tr * 4, co = P_c1[j] + tc * 4;
#pragma unroll
                for (int i = 0; i < 4; ++i)
#pragma unroll
                    for (int q = 0; q < 4; ++q)
                        hb[ro + i][co + q] += fs * pacc[i][q];
            }
        }
    }
    __syncthreads();

    // ---- FWHT along m (reference butterfly order, fp32), 128 rows ----
    for (int half = 1; half < MOUT; half <<= 1) {
#pragma unroll
        for (int p = 0; p < 32; ++p) {          // 128 rows * 64 pairs / 256 thr
            const int pidx = tid + p * 256;
            const int row = pidx >> 6;
            const int t   = pidx & 63;
            const int jj  = ((t & ~(half - 1)) << 1) | (t & (half - 1));
            const float a = hb[row][jj];
            const float b = hb[row][jj + half];
            hb[row][jj]        = a + b;
            hb[row][jj + half] = a - b;
        }
        __syncthreads();
    }

    // ---- sign + store + fragility flag ----
    const float scale = 0.08838834764831844f;   // fp32(1/sqrt(128))
    const int hr  = tid >> 1;                   // hb row 0..127
    const int cb  = (tid & 1) * 64;
    const size_t real_row = (hr < 64) ? (size_t)(br + hr)
                                      : (size_t)(MHALF + br + (hr - 64));
    float mn = 1e30f;
#pragma unroll
    for (int cc = 0; cc < 64; cc += 4) {
        const float4 v = *(const float4*)&hb[hr][cb + cc];
        const float s0 = v.x * scale, s1 = v.y * scale,
                    s2 = v.z * scale, s3 = v.w * scale;
        float4 o;
        o.x = s0 > 0.0f ? 1.0f : 0.0f;
        o.y = s1 > 0.0f ? 1.0f : 0.0f;
        o.z = s2 > 0.0f ? 1.0f : 0.0f;
        o.w = s3 > 0.0f ? 1.0f : 0.0f;
        mn = fminf(mn, fminf(fminf(fabsf(s0), fabsf(s1)),
                             fminf(fabsf(s2), fabsf(s3))));
        *(float4*)(out + real_row * MOUT + cb + cc) = o;
    }
    mn = fminf(mn, __shfl_xor_sync(0xffffffffu, mn, 1));
    if ((tid & 1) == 0) g_flags[real_row] = (mn < TAU) ? 1 : 0;
}

// ---------------- exact fix: one block per row, bit-exact reference chain ----
__global__ void __launch_bounds__(128)
fix_rows_kernel(const float* __restrict__ x, const float* __restrict__ W,
                float* __restrict__ out) {
    const int row = blockIdx.x;
    if (!g_flags[row]) return;

    __shared__ float xs[K_DIM];
    __shared__ float hrow[MOUT];
    const int t = threadIdx.x;

    for (int cc = t; cc < K_DIM / 4; cc += 128)
        *(float4*)&xs[cc * 4] = *(const float4*)&x[(size_t)row * K_DIM + cc * 4];
    __syncthreads();

    float acc = 0.0f;
    const float* wr = W + (size_t)t * K_DIM;
    for (int d = 0; d < K_DIM; ++d)
        acc = fmaf(xs[d], wr[d], acc);
    hrow[t] = acc;
    __syncthreads();

    for (int half = 1; half < MOUT; half <<= 1) {
        if (t < MOUT / 2) {
            const int jj = ((t & ~(half - 1)) << 1) | (t & (half - 1));
            const float a = hrow[jj];
            const float b = hrow[jj + half];
            hrow[jj]        = a + b;
            hrow[jj + half] = a - b;
        }
        __syncthreads();
    }
    out[(size_t)row * MOUT + t] =
        (hrow[t] * 0.08838834764831844f > 0.0f) ? 1.0f : 0.0f;
}

// ---------------- launch ----------------
extern "C" void kernel_launch(void* const* d_in, const int* in_sizes, int n_in,
                              void* d_out, int out_size) {
    const float* x = (const float*)d_in[0];   // [32768, 1024]
    const float* W = (const float*)d_in[1];   // [128, 1024]
    float* out = (float*)d_out;               // [32768, 128]

    cudaFuncSetAttribute(strassen_kernel,
                         cudaFuncAttributeMaxDynamicSharedMemorySize, SM_TOTAL);

    prep_v_kernel<<<(7 * KHALF * NHALF) / 256, 256>>>(W);
    strassen_kernel<<<MHALF / 64, 256, SM_TOTAL>>>(x, out);
    fix_rows_kernel<<<NROWS, 128>>>(x, W, out);
}

// round 11
// speedup vs baseline: 1.3966x; 1.3966x over previous
#include <cuda_runtime.h>
#include <cstdint>

// REWAEncoder: out = (FWHT_128(x @ W^T)/sqrt(128) > 0)
// R11 "Strassen v3": one-level Strassen, K-split, no atomics.
//  k1: prep V-combos
//  k2: 896 CTAs (7 P x 64 mtiles x 2 k-halves), R2-exact 256x64x256 fp32 GEMM,
//      plain STG of the P slice (deterministic)
//  k3: combine (C-quadrant term sums from L2-resident P) + FWHT + sign + flag
//  k4: exact fix of flagged rows (bit-exact reference chain; proven rel_err 0.0)
//
// x [32768,1024] f32, W [128,1024] f32, out [32768,128] f32.

#define K_DIM 1024
#define MOUT  128
#define NROWS 32768
#define MHALF 16384
#define KHALF 512
#define KQ    256          // K per CTA (k-split)
#define NHALF 64
#define TAU   3e-4f

__device__ __align__(16) float g_V[7 * KHALF * NHALF];        // [j][k][n]
__device__ __align__(16) float g_P[14 * MHALF * NHALF];       // [(j,kh)][vrow][n] 58.7MB
__device__ int g_flags[NROWS];

// ---------------- k1: prep V-combos ----------------
// V1=B11+B22 V2=B11 V3=B12-B22 V4=B21-B11 V5=B22 V6=B11+B12 V7=B21+B22
// B[k][n] = W[n][k]
__global__ void prep_kernel(const float* __restrict__ W) {
    const int t = blockIdx.x * blockDim.x + threadIdx.x;   // 0..229375 exact
    const int j = t / (KHALF * NHALF);
    const int r = t % (KHALF * NHALF);
    const int k = r / NHALF;
    const int n = r % NHALF;
    const float b11 = W[(size_t)n * K_DIM + k];
    const float b12 = W[(size_t)(n + NHALF) * K_DIM + k];
    const float b21 = W[(size_t)n * K_DIM + k + KHALF];
    const float b22 = W[(size_t)(n + NHALF) * K_DIM + k + KHALF];
    float v;
    switch (j) {
        case 0: v = b11 + b22; break;
        case 1: v = b11;       break;
        case 2: v = b12 - b22; break;
        case 3: v = b21 - b11; break;
        case 4: v = b22;       break;
        case 5: v = b11 + b12; break;
        default: v = b21 + b22; break;
    }
    g_V[t] = v;
}

// ---------------- k2: P-slice GEMM (R2 mainloop) ----------------
// U_j = x[h1][c1 + k] + s2 * x[h2][c2 + k]   (LUTs verified by R9's passing run)
__constant__ int c_h1[7] = {0, 1, 0, 1, 0, 1, 0};
__constant__ int c_c1[7] = {0, 0, 0, KHALF, 0, 0, KHALF};
__constant__ int c_s2[7] = {1, 1, 0, 0, 1, -1, -1};
__constant__ int c_h2[7] = {1, 1, 0, 0, 0, 0, 1};
__constant__ int c_c2[7] = {KHALF, KHALF, 0, 0, KHALF, 0, KHALF};

#define BMS 256
#define BK  16

__global__ void __launch_bounds__(256, 2)
pgemm_kernel(const float* __restrict__ x) {
    __shared__ float As[BK][BMS];    // 16 KB
    __shared__ float Bs[BK][NHALF];  // 4 KB

    const int tid = threadIdx.x;
    const int kh  = blockIdx.x & 1;        // k-half 0/1
    const int mt  = (blockIdx.x >> 1) & 63;
    const int j   = blockIdx.x >> 7;       // 0..6
    const int vrb = mt * BMS;

    const int tr = tid >> 3;               // rows tr*8..+7 (32 groups)
    const int tc = tid & 7;                // cols tc*8..+7

    const int r0 = tid >> 2;               // staging row 0..63 (4 copies +64p)
    const int q0 = tid & 3;                // staging k-float4

    const int s2 = c_s2[j];
    const float fs2 = (float)s2;
    const int kofs = kh * KQ;
    const float* a1b[4];
    const float* a2b[4];
#pragma unroll
    for (int p = 0; p < 4; ++p) {
        const size_t row = (size_t)vrb + r0 + 64 * p;
        a1b[p] = x + ((size_t)c_h1[j] * MHALF + row) * K_DIM + c_c1[j] + kofs + q0 * 4;
        a2b[p] = x + ((size_t)c_h2[j] * MHALF + row) * K_DIM + c_c2[j] + kofs + q0 * 4;
    }
    const float* vb = g_V + ((size_t)j * KHALF + kofs + (tid >> 4)) * NHALF
                    + (tid & 15) * 4;

    float acc[8][8];
#pragma unroll
    for (int i = 0; i < 8; ++i)
#pragma unroll
        for (int q = 0; q < 8; ++q) acc[i][q] = 0.0f;

    float4 pa[4], pb;
#pragma unroll
    for (int p = 0; p < 4; ++p) {
        float4 a1 = *(const float4*)(a1b[p]);
        if (s2 != 0) {
            float4 a2 = *(const float4*)(a2b[p]);
            a1.x = fmaf(fs2, a2.x, a1.x); a1.y = fmaf(fs2, a2.y, a1.y);
            a1.z = fmaf(fs2, a2.z, a1.z); a1.w = fmaf(fs2, a2.w, a1.w);
        }
        pa[p] = a1;
    }
    pb = *(const float4*)(vb);

    const int nkt = KQ / BK;               // 16
    for (int kt = 0; kt < nkt; ++kt) {
        const int kc = q0 * 4;
#pragma unroll
        for (int p = 0; p < 4; ++p) {
            As[kc + 0][r0 + 64 * p] = pa[p].x;
            As[kc + 1][r0 + 64 * p] = pa[p].y;
            As[kc + 2][r0 + 64 * p] = pa[p].z;
            As[kc + 3][r0 + 64 * p] = pa[p].w;
        }
        *(float4*)&Bs[tid >> 4][(tid & 15) * 4] = pb;
        __syncthreads();

        if (kt + 1 < nkt) {
            const int off = (kt + 1) * BK;
#pragma unroll
            for (int p = 0; p < 4; ++p) {
                float4 a1 = *(const float4*)(a1b[p] + off);
                if (s2 != 0) {
                    float4 a2 = *(const float4*)(a2b[p] + off);
                    a1.x = fmaf(fs2, a2.x, a1.x); a1.y = fmaf(fs2, a2.y, a1.y);
                    a1.z = fmaf(fs2, a2.z, a1.z); a1.w = fmaf(fs2, a2.w, a1.w);
                }
                pa[p] = a1;
            }
            pb = *(const float4*)(vb + (size_t)off * NHALF);
        }

        // sequential k accumulation (one fp32 fma chain per P element)
#pragma unroll
        for (int k = 0; k < BK; ++k) {
            const float4 a0 = *(const float4*)&As[k][tr * 8];
            const float4 a1 = *(const float4*)&As[k][tr * 8 + 4];
            const float4 b0 = *(const float4*)&Bs[k][tc * 8];
            const float4 b1 = *(const float4*)&Bs[k][tc * 8 + 4];
            const float av[8] = {a0.x, a0.y, a0.z, a0.w, a1.x, a1.y, a1.z, a1.w};
            const float bv[8] = {b0.x, b0.y, b0.z, b0.w, b1.x, b1.y, b1.z, b1.w};
#pragma unroll
            for (int i = 0; i < 8; ++i)
#pragma unroll
                for (int q = 0; q < 8; ++q)
                    acc[i][q] = fmaf(av[i], bv[q], acc[i][q]);
        }
        __syncthreads();
    }

    // epilogue: plain STG of this P slice (CTA owns region; deterministic)
    const size_t pbase = ((size_t)(j * 2 + kh) * MHALF + vrb + tr * 8) * NHALF
                       + tc * 8;
#pragma unroll
    for (int i = 0; i < 8; ++i) {
        float* prow = g_P + pbase + (size_t)i * NHALF;
        *(float4*)(prow)     = make_float4(acc[i][0], acc[i][1], acc[i][2], acc[i][3]);
        *(float4*)(prow + 4) = make_float4(acc[i][4], acc[i][5], acc[i][6], acc[i][7]);
    }
}

// ---------------- k3: combine + FWHT + sign + flag ----------------
// C11=P1+P4-P5+P7  C12=P3+P5  C21=P2+P4  C22=P1-P2+P3+P6
#define HB_PITCH 132
__constant__ int t_nL[2]  = {4, 2};                 // [top? 0 : 1] term counts, left
__constant__ int t_jL[2][4] = {{0, 3, 4, 6}, {1, 3, 1, 3}};
__constant__ float t_sL[2][4] = {{1.f, 1.f, -1.f, 1.f}, {1.f, 1.f, 0.f, 0.f}};
__constant__ int t_nR[2]  = {2, 4};
__constant__ int t_jR[2][4] = {{2, 4, 2, 4}, {0, 1, 2, 5}};
__constant__ float t_sR[2][4] = {{1.f, 1.f, 0.f, 0.f}, {1.f, -1.f, 1.f, 1.f}};

__global__ void __launch_bounds__(256, 2)
combine_kernel(float* __restrict__ out) {
    __shared__ float hb[128][HB_PITCH];
    const int tid = threadIdx.x;
    const int block_row = blockIdx.x * 128;
    const int bot = (block_row >= MHALF) ? 1 : 0;
    const int vr0 = bot ? (block_row - MHALF) : block_row;

    // build hb: left (cols 0..63) then right (cols 64..127)
#pragma unroll
    for (int h = 0; h < 2; ++h) {
        const int nt = h ? t_nR[bot] : t_nL[bot];
#pragma unroll
        for (int p = 0; p < 8; ++p) {               // 128 rows * 16 f4 / 256 thr
            const int f4  = tid + p * 256;
            const int row = f4 >> 4;
            const int c   = (f4 & 15) * 4;
            float4 a = make_float4(0.f, 0.f, 0.f, 0.f);
            for (int t = 0; t < nt; ++t) {
                const int jj   = h ? t_jR[bot][t] : t_jL[bot][t];
                const float s  = h ? t_sR[bot][t] : t_sL[bot][t];
                const size_t b0 = ((size_t)(jj * 2) * MHALF + vr0 + row) * NHALF + c;
                const float4 v0 = *(const float4*)(g_P + b0);
                const float4 v1 = *(const float4*)(g_P + b0 + (size_t)MHALF * NHALF);
                a.x = fmaf(s, v0.x + v1.x, a.x);
                a.y = fmaf(s, v0.y + v1.y, a.y);
                a.z = fmaf(s, v0.z + v1.z, a.z);
                a.w = fmaf(s, v0.w + v1.w, a.w);
            }
            *(float4*)&hb[row][h * 64 + c] = a;
        }
    }
    __syncthreads();

    // FWHT along m, reference butterfly order (fp32)
    for (int half = 1; half < MOUT; half <<= 1) {
#pragma unroll
        for (int p = 0; p < 32; ++p) {
            const int pidx = tid + p * 256;
            const int row = pidx >> 6;
            const int t   = pidx & 63;
            const int jj  = ((t & ~(half - 1)) << 1) | (t & (half - 1));
            const float a = hb[row][jj];
            const float b = hb[row][jj + half];
            hb[row][jj]        = a + b;
            hb[row][jj + half] = a - b;
        }
        __syncthreads();
    }

    const float scale = 0.08838834764831844f;   // fp32(1/sqrt(128))
    const int hr = tid >> 1;
    const int cb = (tid & 1) * 64;
    float mn = 1e30f;
#pragma unroll
    for (int cc = 0; cc < 64; cc += 4) {
        const float4 v = *(const float4*)&hb[hr][cb + cc];
        const float s0 = v.x * scale, s1 = v.y * scale,
                    s2 = v.z * scale, s3 = v.w * scale;
        float4 o;
        o.x = s0 > 0.0f ? 1.0f : 0.0f;
        o.y = s1 > 0.0f ? 1.0f : 0.0f;
        o.z = s2 > 0.0f ? 1.0f : 0.0f;
        o.w = s3 > 0.0f ? 1.0f : 0.0f;
        mn = fminf(mn, fminf(fminf(fabsf(s0), fabsf(s1)),
                             fminf(fabsf(s2), fabsf(s3))));
        *(float4*)(out + (size_t)(block_row + hr) * MOUT + cb + cc) = o;
    }
    mn = fminf(mn, __shfl_xor_sync(0xffffffffu, mn, 1));
    if ((tid & 1) == 0) g_flags[block_row + hr] = (mn < TAU) ? 1 : 0;
}

// ---------------- k4: exact fix (bit-exact reference chain; proven) ----------
__global__ void __launch_bounds__(128)
fix_rows_kernel(const float* __restrict__ x, const float* __restrict__ W,
                float* __restrict__ out) {
    const int row = blockIdx.x;
    if (!g_flags[row]) return;

    __shared__ float xs[K_DIM];
    __shared__ float hrow[MOUT];
    const int t = threadIdx.x;

    for (int cc = t; cc < K_DIM / 4; cc += 128)
        *(float4*)&xs[cc * 4] = *(const float4*)&x[(size_t)row * K_DIM + cc * 4];
    __syncthreads();

    float acc = 0.0f;
    const float* wr = W + (size_t)t * K_DIM;
    for (int d = 0; d < K_DIM; ++d)
        acc = fmaf(xs[d], wr[d], acc);
    hrow[t] = acc;
    __syncthreads();

    for (int half = 1; half < MOUT; half <<= 1) {
        if (t < MOUT / 2) {
            const int jj = ((t & ~(half - 1)) << 1) | (t & (half - 1));
            const float a = hrow[jj];
            const float b = hrow[jj + half];
            hrow[jj]        = a + b;
            hrow[jj + half] = a - b;
        }
        __syncthreads();
    }
    out[(size_t)row * MOUT + t] =
        (hrow[t] * 0.08838834764831844f > 0.0f) ? 1.0f : 0.0f;
}

// ---------------- launch ----------------
extern "C" void kernel_launch(void* const* d_in, const int* in_sizes, int n_in,
                              void* d_out, int out_size) {
    const float* x = (const float*)d_in[0];   // [32768, 1024]
    const float* W = (const float*)d_in[1];   // [128, 1024]
    float* out = (float*)d_out;               // [32768, 128]

    prep_kernel<<<896, 256>>>(W);                  // V combos (229376 threads exact)
    pgemm_kernel<<<7 * 64 * 2, 256>>>(x);          // P slices -> g_P (plain STG)
    combine_kernel<<<NROWS / 128, 256>>>(out);     // term sums + FWHT + sign + flag
    fix_rows_kernel<<<NROWS, 128>>>(x, W, out);    // bit-exact repair
}

// round 12
// speedup vs baseline: 5.8015x; 4.1541x over previous
#include <cuda_runtime.h>
#include <cuda_bf16.h>

// out[row,m] = ( fp32FWHT_m( sum_d fma-chain x[row,d]*W[m,d] ) * (1/sqrt(128)) > 0 ) ? 1 : 0
//
// FINAL (committed): bit-exact vs the CPU fp32 reference (rel_err == 0.0):
//  - GEMM: ONE fp32 accumulator per output, strictly sequential fmaf over d=0..1023
//    (matches the reference's per-output fma chain).
//  - FWHT: identical butterfly pairing/order as the reference, fp32 a+b / a-b,
//    then multiply by the fp32-rounded 1/sqrt(128), then >0.
//
// This kernel runs at ~94-100% of the sm_103a fp32 issue roofline
// (FFMA rt_SMSP=2 -> 64 lane-FMA/cyc/SM). All alternative routes measured dead:
// tcgen05 (ptxas targets base sm_103), mma.sync (FFMA-emulated, 3x cost),
// FFMA2 (2 datapath slots), Strassen (plumbing > savings), int8/fp16 (numerics).
//
// x [32768,1024] fp32, W [128,1024] fp32, out [32768,128] fp32.

#define MOUT 128
#define BM   128
#define BK   16

__global__ void __launch_bounds__(256, 2)
gemm_fwht_sign_kernel(const float* __restrict__ x, const float* __restrict__ W,
                      float* __restrict__ out, int K) {
    // smem: GEMM tiles overlaid with the FWHT row buffer (used after GEMM done)
    __shared__ __align__(16) char smbuf[64 * (MOUT + 4) * 4];   // 33792 B
    float (*As)[BM]       = reinterpret_cast<float(*)[BM]>(smbuf);
    float (*Bs)[MOUT]     = reinterpret_cast<float(*)[MOUT]>(smbuf + BK * BM * 4);
    float (*hb)[MOUT + 4] = reinterpret_cast<float(*)[MOUT + 4]>(smbuf);

    const int tid = threadIdx.x;      // 0..255
    const int tr  = tid >> 4;         // 0..15
    const int tc  = tid & 15;         // 0..15
    const int block_row = blockIdx.x * BM;

    const int r0 = tid >> 2;          // 0..63
    const int q0 = tid & 3;

    const float4* xA0 = (const float4*)(x + (size_t)(block_row + r0) * K) + q0;
    const float4* xA1 = (const float4*)(x + (size_t)(block_row + r0 + 64) * K) + q0;
    const float4* wB0 = (const float4*)(W + (size_t)r0 * K) + q0;
    const float4* wB1 = (const float4*)(W + (size_t)(r0 + 64) * K) + q0;

    float acc[8][8];
#pragma unroll
    for (int i = 0; i < 8; ++i)
#pragma unroll
        for (int j = 0; j < 8; ++j) acc[i][j] = 0.0f;

    const int nkt = K / BK;           // 64

    float4 pa0 = xA0[0];
    float4 pa1 = xA1[0];
    float4 pb0 = wB0[0];
    float4 pb1 = wB1[0];

    for (int kt = 0; kt < nkt; ++kt) {
        const int kc = q0 * 4;
        As[kc + 0][r0] = pa0.x; As[kc + 1][r0] = pa0.y;
        As[kc + 2][r0] = pa0.z; As[kc + 3][r0] = pa0.w;
        As[kc + 0][r0 + 64] = pa1.x; As[kc + 1][r0 + 64] = pa1.y;
        As[kc + 2][r0 + 64] = pa1.z; As[kc + 3][r0 + 64] = pa1.w;
        Bs[kc + 0][r0] = pb0.x; Bs[kc + 1][r0] = pb0.y;
        Bs[kc + 2][r0] = pb0.z; Bs[kc + 3][r0] = pb0.w;
        Bs[kc + 0][r0 + 64] = pb1.x; Bs[kc + 1][r0 + 64] = pb1.y;
        Bs[kc + 2][r0 + 64] = pb1.z; Bs[kc + 3][r0 + 64] = pb1.w;
        __syncthreads();

        if (kt + 1 < nkt) {
            const int off = (kt + 1) * (BK / 4);
            pa0 = xA0[off]; pa1 = xA1[off];
            pb0 = wB0[off]; pb1 = wB1[off];
        }

        // strictly sequential k accumulation: d ascending within tile, tiles ascending
#pragma unroll
        for (int k = 0; k < BK; ++k) {
            float4 a0 = *(const float4*)&As[k][tr * 8];
            float4 a1 = *(const float4*)&As[k][tr * 8 + 4];
            float4 b0 = *(const float4*)&Bs[k][tc * 8];
            float4 b1 = *(const float4*)&Bs[k][tc * 8 + 4];
            float av[8] = {a0.x, a0.y, a0.z, a0.w, a1.x, a1.y, a1.z, a1.w};
            float bv[8] = {b0.x, b0.y, b0.z, b0.w, b1.x, b1.y, b1.z, b1.w};
#pragma unroll
            for (int i = 0; i < 8; ++i)
#pragma unroll
                for (int j = 0; j < 8; ++j)
                    acc[i][j] = fmaf(av[i], bv[j], acc[i][j]);
        }
        __syncthreads();
    }

    // ---- epilogue: fp32 FWHT along m (reference butterfly order) + sign ----
    const float scale = 0.08838834764831844f;   // fp32( 1/sqrt(128) )

    for (int hs = 0; hs < 2; ++hs) {            // rows [0,64) then [64,128)
        __syncthreads();
        if ((tr >> 3) == hs) {
            const int rbase = (tr & 7) * 8;
#pragma unroll
            for (int i = 0; i < 8; ++i)
#pragma unroll
                for (int j = 0; j < 8; ++j)
                    hb[rbase + i][tc * 8 + j] = acc[i][j];
        }
        __syncthreads();

        for (int half = 1; half < MOUT; half <<= 1) {
#pragma unroll
            for (int p = 0; p < 16; ++p) {      // 4096 pairs / 256 threads
                const int pidx = tid + p * 256;
                const int row = pidx >> 6;
                const int t   = pidx & 63;
                const int j   = ((t & ~(half - 1)) << 1) | (t & (half - 1));
                const float a = hb[row][j];
                const float b = hb[row][j + half];
                hb[row][j]        = a + b;
                hb[row][j + half] = a - b;
            }
            __syncthreads();
        }

#pragma unroll
        for (int p = 0; p < 8; ++p) {           // 2048 float4 stores
            const int f4  = tid + p * 256;
            const int row = f4 >> 5;
            const int c   = (f4 & 31) * 4;
            float4 v = *(const float4*)&hb[row][c];
            float4 o;
            o.x = (v.x * scale > 0.0f) ? 1.0f : 0.0f;
            o.y = (v.y * scale > 0.0f) ? 1.0f : 0.0f;
            o.z = (v.z * scale > 0.0f) ? 1.0f : 0.0f;
            o.w = (v.w * scale > 0.0f) ? 1.0f : 0.0f;
            *(float4*)(out + (size_t)(block_row + hs * 64 + row) * MOUT + c) = o;
        }
    }
}

extern "C" void kernel_launch(void* const* d_in, const int* in_sizes, int n_in,
                              void* d_out, int out_size) {
    const float* x = (const float*)d_in[0];   // [rows, K]
    const float* W = (const float*)d_in[1];   // [128, K]
    float* out = (float*)d_out;               // [rows, 128]

    const int K = in_sizes[1] / MOUT;         // 1024
    const int rows = in_sizes[0] / K;         // 32768

    gemm_fwht_sign_kernel<<<rows / BM, 256>>>(x, W, out, K);
}